// round 15
// baseline (speedup 1.0000x reference)
#include <cuda_runtime.h>
#include <cuda_fp16.h>
#include <cstdint>

#define HC 100
typedef unsigned long long ull;

__device__ __half g_qkv[(size_t)100000 * 300];   // q|k|v fp16, gathered
__device__ float  g_skip[(size_t)100000 * HC];   // skip fp32, streamed
__device__ float  g_acc[(size_t)100000 * HC];
__device__ float  g_denom[(size_t)100000 * 2];

__device__ __forceinline__ void red2(float* p, float a, float b) {
    asm volatile("red.global.add.v2.f32 [%0], {%1, %2};" :: "l"(p), "f"(a), "f"(b) : "memory");
}
__device__ __forceinline__ void red4(float* p, float a, float b, float c, float d) {
    asm volatile("red.global.add.v4.f32 [%0], {%1, %2, %3, %4};"
                 :: "l"(p), "f"(a), "f"(b), "f"(c), "f"(d) : "memory");
}
__device__ __forceinline__ void prefetchL2(const void* p) {
    asm volatile("prefetch.global.L2 [%0];" :: "l"(p));
}
__device__ __forceinline__ uint32_t smem_u32(const void* p) {
    uint32_t a;
    asm("{ .reg .u64 t; cvta.to.shared.u64 t, %1; cvt.u32.u64 %0, t; }" : "=r"(a) : "l"(p));
    return a;
}
__device__ __forceinline__ void ldsm_x4(uint32_t* r, uint32_t a) {
    asm volatile("ldmatrix.sync.aligned.m8n8.x4.shared.b16 {%0,%1,%2,%3}, [%4];"
                 : "=r"(r[0]), "=r"(r[1]), "=r"(r[2]), "=r"(r[3]) : "r"(a));
}
__device__ __forceinline__ void ldsm_x2(uint32_t* r, uint32_t a) {
    asm volatile("ldmatrix.sync.aligned.m8n8.x2.shared.b16 {%0,%1}, [%2];"
                 : "=r"(r[0]), "=r"(r[1]) : "r"(a));
}
__device__ __forceinline__ void mma16816(float* c, const uint32_t* a, const uint32_t* b) {
    asm volatile("mma.sync.aligned.m16n8k16.row.col.f32.f16.f16.f32 "
                 "{%0,%1,%2,%3}, {%4,%5,%6,%7}, {%8,%9}, {%0,%1,%2,%3};"
                 : "+f"(c[0]), "+f"(c[1]), "+f"(c[2]), "+f"(c[3])
                 : "r"(a[0]), "r"(a[1]), "r"(a[2]), "r"(a[3]), "r"(b[0]), "r"(b[1]));
}
__device__ __forceinline__ float4 h4_to_f4(uint2 u) {
    __half2* ph = reinterpret_cast<__half2*>(&u);
    float2 a = __half22float2(ph[0]);
    float2 b = __half22float2(ph[1]);
    return make_float4(a.x, a.y, b.x, b.y);
}

// ---------------------------------------------------------------------------
// Dummy no-op kernels: shift the ncu capture slot so slot-3 == k_edge.
// ---------------------------------------------------------------------------
__global__ void k_dummy0() {}
__global__ void k_dummy1() {}

// ---------------------------------------------------------------------------
// Node projections: HMMA fp16 (R13). q|k|v fp16, skip fp32. Zeroes acc/denom.
// ---------------------------------------------------------------------------
#define NP_W   0
#define NP_B   96000
#define NP_A   97600
#define SMEM_NP_BYTES 112960
#define NPSTR  240

__global__ void __launch_bounds__(256, 2) k_nproj(
    const float* __restrict__ x,
    const float* __restrict__ Wq, const float* __restrict__ bq,
    const float* __restrict__ Wk, const float* __restrict__ bk,
    const float* __restrict__ Wv, const float* __restrict__ bv,
    const float* __restrict__ Ws, const float* __restrict__ bs,
    int n)
{
    extern __shared__ char smb[];
    uint32_t sbase = smem_u32(smb);
    int tid = threadIdx.x;
    int warp = tid >> 5, lane = tid & 31;
    int gtid = blockIdx.x * 256 + tid;
    int gstep = gridDim.x * 256;

    {
        int na = n * 25;
        int tot = na + n;
        float4 z4 = make_float4(0.f, 0.f, 0.f, 0.f);
        for (int i = gtid; i < tot; i += gstep) {
            if (i < na) ((float4*)g_acc)[i] = z4;
            else        ((float2*)g_denom)[i - na] = make_float2(0.f, 0.f);
        }
    }

    for (int idx = tid; idx < 400 * 100; idx += 256) {
        int c = idx / 100, j = idx - c * 100;
        float v;
        if      (c < 100) v = Wq[j * 100 + c];
        else if (c < 200) v = Wk[j * 100 + c - 100];
        else if (c < 300) v = Wv[j * 100 + c - 200];
        else              v = Ws[j * 100 + c - 300];
        *(__half*)(smb + NP_W + c * NPSTR + j * 2) = __float2half_rn(v);
    }
    for (int idx = tid; idx < 400 * 10; idx += 256) {
        int c = idx / 10, z = idx - c * 10;
        *(uint32_t*)(smb + NP_W + c * NPSTR + 200 + z * 4) = 0u;
    }
    {
        float* bsm = (float*)(smb + NP_B);
        for (int i = tid; i < 400; i += 256) {
            bsm[i] = (i < 100) ? bq[i] : (i < 200) ? bk[i - 100]
                   : (i < 300) ? bv[i - 200] : bs[i - 300];
        }
    }
    __syncthreads();

    const float* bsm = (const float*)(smb + NP_B);
    int mrow = (warp & 3) * 16;
    int nfbase = (warp >> 2) * 25;

    int ntiles = (n + 63) >> 6;
    for (int tile = blockIdx.x; tile < ntiles; tile += gridDim.x) {
        int nbase = tile << 6;
        __syncthreads();

        for (int idx = tid; idx < 64 * 25; idx += 256) {
            int r = idx / 25, q = idx - r * 25;
            int nd = nbase + r; if (nd >= n) nd = n - 1;
            float4 v = ((const float4*)(x + (size_t)nd * 100))[q];
            __half2 h0, h1;
            h0.x = __float2half_rn(v.x); h0.y = __float2half_rn(v.y);
            h1.x = __float2half_rn(v.z); h1.y = __float2half_rn(v.w);
            uint2 p;
            p.x = *reinterpret_cast<uint32_t*>(&h0);
            p.y = *reinterpret_cast<uint32_t*>(&h1);
            *(uint2*)(smb + NP_A + r * NPSTR + q * 8) = p;
        }
        for (int idx = tid; idx < 64 * 10; idx += 256) {
            int r = idx / 10, z = idx - r * 10;
            *(uint32_t*)(smb + NP_A + r * NPSTR + 200 + z * 4) = 0u;
        }
        __syncthreads();

        uint32_t abase = sbase + NP_A
                       + (uint32_t)((mrow + (lane & 15)) * NPSTR + (lane >> 4) * 16);
        uint32_t af[7][4];
        #pragma unroll
        for (int k = 0; k < 7; k++) ldsm_x4(af[k], abase + k * 32);

        int rowA = mrow + (lane >> 2);
        int nd0 = nbase + rowA;
        int nd1 = nd0 + 8;

        #pragma unroll 1
        for (int nf = 0; nf < 25; nf++) {
            int nfg = nfbase + nf;
            uint32_t bb = sbase + NP_W
                + (uint32_t)((nfg * 8 + (lane & 7)) * NPSTR + (lane >> 3) * 16);
            float ac[4] = {0.f, 0.f, 0.f, 0.f};
            #pragma unroll
            for (int kk = 0; kk < 3; kk++) {
                uint32_t bh[4];
                ldsm_x4(bh, bb + kk * 64);
                mma16816(ac, af[2 * kk],     bh);
                mma16816(ac, af[2 * kk + 1], bh + 2);
            }
            uint32_t b2[2];
            ldsm_x2(b2, bb + 192);
            mma16816(ac, af[6], b2);

            int col = nfg * 8 + 2 * (lane & 3);
            float bx = bsm[col], by = bsm[col + 1];
            if (col < 300) {
                __half2 h0, h1;
                h0.x = __float2half_rn(ac[0] + bx); h0.y = __float2half_rn(ac[1] + by);
                h1.x = __float2half_rn(ac[2] + bx); h1.y = __float2half_rn(ac[3] + by);
                if (nd0 < n) *(__half2*)(g_qkv + (size_t)nd0 * 300 + col) = h0;
                if (nd1 < n) *(__half2*)(g_qkv + (size_t)nd1 * 300 + col) = h1;
            } else {
                int sc = col - 300;
                if (nd0 < n)
                    *(float2*)(g_skip + (size_t)nd0 * 100 + sc) =
                        make_float2(ac[0] + bx, ac[1] + by);
                if (nd1 < n)
                    *(float2*)(g_skip + (size_t)nd1 * 100 + sc) =
                        make_float2(ac[2] + bx, ac[3] + by);
            }
        }
    }
}

// ---------------------------------------------------------------------------
// Edge kernel (R13 best): HMMA fp16, 64-edge tiles, 2 CTAs/SM, fp16 gathers
// ---------------------------------------------------------------------------
#define SM_W   0
#define SM_A   58240
#define SM_SRC 94080
#define SM_DST 94336
#define SM_REL 94592
#define SM_WTB 94848
#define SMEM_EDGE_BYTES 95648
#define ETILE 64
#define ESTR  108

__device__ __forceinline__ void build_tile(
    char* smb, const float* __restrict__ msg, int ebase, int ne, int tid)
{
    const float* wtb = (const float*)(smb + SM_WTB);
    const float* rel = (const float*)(smb + SM_REL);
    for (int idx = tid; idx < ETILE * 34; idx += 256) {
        int r = idx / 34, g = idx - r * 34;
        int j0 = g * 8;
        int eg = ebase + r; if (eg >= ne) eg = ne - 1;
        float v[8];
        if (j0 + 8 <= 100) {
            float rr = rel[r];
            #pragma unroll
            for (int i = 0; i < 8; i++)
                v[i] = __cosf(fmaf(rr, wtb[j0 + i], wtb[100 + j0 + i]));
        } else if (j0 >= 104) {
            const float4* m4 = (const float4*)(msg + (size_t)eg * 172 + (j0 - 100));
            float4 a = m4[0], b = m4[1];
            v[0] = a.x; v[1] = a.y; v[2] = a.z; v[3] = a.w;
            v[4] = b.x; v[5] = b.y; v[6] = b.z; v[7] = b.w;
        } else {
            float rr = rel[r];
            const float* mrow = msg + (size_t)eg * 172;
            #pragma unroll
            for (int i = 0; i < 8; i++) {
                int j = j0 + i;
                v[i] = (j < 100) ? __cosf(fmaf(rr, wtb[j], wtb[100 + j])) : mrow[j - 100];
            }
        }
        uint32_t p[4];
        #pragma unroll
        for (int i = 0; i < 4; i++) {
            __half2 h;
            h.x = __float2half_rn(v[2 * i]);
            h.y = __float2half_rn(v[2 * i + 1]);
            p[i] = *reinterpret_cast<uint32_t*>(&h);
        }
        *(uint4*)(smb + SM_A + r * 560 + j0 * 2) = make_uint4(p[0], p[1], p[2], p[3]);
    }
}

__global__ void __launch_bounds__(256, 2) k_edge(
    const float* __restrict__ lu, const float* __restrict__ t,
    const float* __restrict__ msg,
    const float* __restrict__ Wt, const float* __restrict__ bt,
    const float* __restrict__ We, const int* __restrict__ ei,
    int n, int ne)
{
    extern __shared__ char smb[];
    uint32_t sbase = smem_u32(smb);
    int tid = threadIdx.x;
    int warp = tid >> 5, lane = tid & 31;

    for (int idx = tid; idx < 104 * 272; idx += 256) {
        int c = idx / 272, j = idx - c * 272;
        float w = (c < 100) ? We[j * 100 + c] : 0.0f;
        *(__half*)(smb + SM_W + c * 560 + j * 2) = __float2half_rn(w);
    }
    {
        float* wtb = (float*)(smb + SM_WTB);
        for (int i = tid; i < 100; i += 256) { wtb[i] = Wt[i]; wtb[100 + i] = bt[i]; }
    }
    __syncthreads();

    int* s_src = (int*)(smb + SM_SRC);
    int* s_dst = (int*)(smb + SM_DST);
    float* s_rel = (float*)(smb + SM_REL);
    float* es = (float*)(smb + SM_A);
    const float SCALE = 0.14142135623730951f;
    int lq = (lane < 25) ? lane : 24;

    int mrow = (warp & 3) * 16;
    int nf0  = (warp >> 2) * 7;
    int nfe  = (warp >> 2) ? 13 : 7;

    int ntiles = (ne + ETILE - 1) / ETILE;
    for (int tile = blockIdx.x; tile < ntiles; tile += gridDim.x) {
        int ebase = tile * ETILE;
        __syncthreads();

        if (tid < ETILE) {
            int eg = ebase + tid;
            bool valid = eg < ne;
            int eidx = valid ? eg : 0;
            int s = ei[eidx], d = ei[ne + eidx];
            s_src[tid] = s; s_dst[tid] = d;
            s_rel[tid] = valid ? (lu[s] - t[eidx]) : 0.0f;
            if (valid) {
                const char* qb = (const char*)(g_qkv + (size_t)d * 300);
                const char* kb = (const char*)(g_qkv + (size_t)s * 300 + 100);
                prefetchL2(qb); prefetchL2(qb + 128);
                prefetchL2(kb); prefetchL2(kb + 128);
                prefetchL2(kb + 256); prefetchL2(kb + 384);
            }
        }
        __syncthreads();

        build_tile(smb, msg, ebase, ne, tid);
        __syncthreads();

        float acc[7][4];
        #pragma unroll
        for (int nf = 0; nf < 7; nf++) {
            acc[nf][0] = 0.f; acc[nf][1] = 0.f; acc[nf][2] = 0.f; acc[nf][3] = 0.f;
        }

        {
            uint32_t abase = sbase + SM_A
                           + (uint32_t)((mrow + (lane & 15)) * 560 + (lane >> 4) * 16);
            uint32_t af[17][4];
            #pragma unroll
            for (int k = 0; k < 17; k++) ldsm_x4(af[k], abase + k * 32);

            #pragma unroll 1
            for (int nf = nf0; nf < nfe; nf++) {
                float* ac = acc[nf - nf0];
                uint32_t bb = sbase + SM_W
                    + (uint32_t)((nf * 8 + (lane & 7)) * 560 + (lane >> 3) * 16);
                #pragma unroll
                for (int kk = 0; kk < 8; kk++) {
                    uint32_t bh[4];
                    ldsm_x4(bh, bb + kk * 64);
                    mma16816(ac, af[2 * kk],     bh);
                    mma16816(ac, af[2 * kk + 1], bh + 2);
                }
                uint32_t b2[2];
                ldsm_x2(b2, bb + 512);
                mma16816(ac, af[16], b2);
            }
        }
        __syncthreads();

        {
            int rowA = mrow + (lane >> 2);
            #pragma unroll 1
            for (int nf = nf0; nf < nfe; nf++) {
                float* ac = acc[nf - nf0];
                int col = nf * 8 + 2 * (lane & 3);
                *(float2*)(es + rowA * ESTR + col)       = make_float2(ac[0], ac[1]);
                *(float2*)(es + (rowA + 8) * ESTR + col) = make_float2(ac[2], ac[3]);
            }
        }
        __syncthreads();

        #pragma unroll 1
        for (int i = 0; i < 8; i += 4) {
            int er0 = warp * 8 + i;
            if (ebase + er0 >= ne) break;
            int srcs[4], dsts[4];
            bool val[4];
            #pragma unroll
            for (int e = 0; e < 4; e++) {
                int er = er0 + e;
                val[e] = (ebase + er) < ne;
                int eri = val[e] ? er : er0;
                srcs[e] = s_src[eri]; dsts[e] = s_dst[eri];
            }
            float4 e4[4], q4[4], k4[4], v4[4];
            float dd[8];
            #pragma unroll
            for (int e = 0; e < 4; e++) {
                e4[e] = make_float4(0,0,0,0);
                q4[e] = e4[e]; k4[e] = e4[e]; v4[e] = e4[e];
                dd[2*e] = 0.f; dd[2*e+1] = 0.f;
            }
            if (lane < 25) {
                #pragma unroll
                for (int e = 0; e < 4; e++) {
                    e4[e] = *(const float4*)(es + (er0 + e) * ESTR + lq * 4);
                    q4[e] = h4_to_f4(*(const uint2*)(g_qkv + (size_t)dsts[e] * 300 + lq * 4));
                    k4[e] = h4_to_f4(*(const uint2*)(g_qkv + (size_t)srcs[e] * 300 + 100 + lq * 4));
                    v4[e] = h4_to_f4(*(const uint2*)(g_qkv + (size_t)srcs[e] * 300 + 200 + lq * 4));
                }
                #pragma unroll
                for (int e = 0; e < 4; e++) {
                    dd[2*e]   = q4[e].x * (k4[e].x + e4[e].x) + q4[e].y * (k4[e].y + e4[e].y);
                    dd[2*e+1] = q4[e].z * (k4[e].z + e4[e].z) + q4[e].w * (k4[e].w + e4[e].w);
                }
            }
            float p[8];
            #pragma unroll
            for (int e = 0; e < 4; e++) {
                p[2*e]   = ((lane < 13) ? dd[2*e] : 0.0f) + ((lane < 12) ? dd[2*e+1] : 0.0f);
                p[2*e+1] = ((lane < 13) ? 0.0f : dd[2*e]) + ((lane < 12) ? 0.0f : dd[2*e+1]);
            }
            #pragma unroll
            for (int o = 16; o > 0; o >>= 1) {
                #pragma unroll
                for (int j = 0; j < 8; j++)
                    p[j] += __shfl_xor_sync(0xffffffffu, p[j], o);
            }
            float ex[8];
            #pragma unroll
            for (int j = 0; j < 8; j++) ex[j] = __expf(p[j] * SCALE);

            if (lane < 4) {
                int e = lane;
                if (val[e]) red2(&g_denom[(size_t)dsts[e] * 2], ex[2*e], ex[2*e+1]);
            }
            if (lane < 25) {
                #pragma unroll
                for (int e = 0; e < 4; e++) {
                    if (!val[e]) continue;
                    float w0 = (lane < 13) ? ex[2*e] : ex[2*e+1];
                    float w1 = (lane < 12) ? ex[2*e] : ex[2*e+1];
                    red4(g_acc + (size_t)dsts[e] * 100 + lq * 4,
                         w0 * (v4[e].x + e4[e].x), w0 * (v4[e].y + e4[e].y),
                         w1 * (v4[e].z + e4[e].z), w1 * (v4[e].w + e4[e].w));
                }
            }
        }
    }
}

// ---------------------------------------------------------------------------
__global__ void k_final(float* __restrict__ out, int n) {
    int tot = n * 25;
    for (int i = blockIdx.x * blockDim.x + threadIdx.x; i < tot;
         i += gridDim.x * blockDim.x) {
        int nd = i / 25, q = i % 25;
        float den0 = g_denom[(size_t)nd * 2 + 0];
        float den1 = g_denom[(size_t)nd * 2 + 1];
        float dxy = (q < 13) ? den0 : den1;
        float dzw = (q < 12) ? den0 : den1;
        float rxy = (dxy > 0.0f) ? (1.0f / dxy) : 0.0f;
        float rzw = (dzw > 0.0f) ? (1.0f / dzw) : 0.0f;
        float4 a4 = ((const float4*)g_acc)[i];
        float4 sk = ((const float4*)g_skip)[i];
        float4 o;
        o.x = a4.x * rxy + sk.x;
        o.y = a4.y * rxy + sk.y;
        o.z = a4.z * rzw + sk.z;
        o.w = a4.w * rzw + sk.w;
        ((float4*)out)[i] = o;
    }
}

// ---------------------------------------------------------------------------
extern "C" void kernel_launch(void* const* d_in, const int* in_sizes, int n_in,
                              void* d_out, int out_size) {
    const float* x   = (const float*)d_in[0];
    const float* lu  = (const float*)d_in[1];
    const float* t   = (const float*)d_in[2];
    const float* msg = (const float*)d_in[3];
    const float* Wt  = (const float*)d_in[4];
    const float* bt  = (const float*)d_in[5];
    const float* Wq  = (const float*)d_in[6];
    const float* bq  = (const float*)d_in[7];
    const float* Wk  = (const float*)d_in[8];
    const float* bk  = (const float*)d_in[9];
    const float* Wv  = (const float*)d_in[10];
    const float* bv  = (const float*)d_in[11];
    const float* We  = (const float*)d_in[12];
    const float* Ws  = (const float*)d_in[13];
    const float* bs  = (const float*)d_in[14];
    const int*   ei  = (const int*)d_in[15];

    int n  = in_sizes[1];
    int ne = in_sizes[2];
    float* out = (float*)d_out;

    int dev = 0;
    cudaGetDevice(&dev);
    int nsm = 148;
    cudaDeviceGetAttribute(&nsm, cudaDevAttrMultiProcessorCount, dev);

    cudaFuncSetAttribute(k_nproj, cudaFuncAttributeMaxDynamicSharedMemorySize, SMEM_NP_BYTES);
    cudaFuncSetAttribute(k_edge,  cudaFuncAttributeMaxDynamicSharedMemorySize, SMEM_EDGE_BYTES);

    // two no-op launches to shift ncu's fixed capture slot onto k_edge
    k_dummy0<<<1, 32>>>();
    k_dummy1<<<1, 32>>>();
    k_nproj<<<nsm * 2, 256, SMEM_NP_BYTES>>>(x, Wq, bq, Wk, bk, Wv, bv, Ws, bs, n);
    k_edge<<<nsm * 2, 256, SMEM_EDGE_BYTES>>>(lu, t, msg, Wt, bt, We, ei, n, ne);
    k_final<<<4096, 256>>>(out, n);
}

// round 16
// speedup vs baseline: 1.6983x; 1.6983x over previous
#include <cuda_runtime.h>
#include <cuda_fp16.h>
#include <cstdint>

#define HC 100
typedef unsigned long long ull;

__device__ __half g_qkv[(size_t)100000 * 300];   // q|k|v fp16, gathered
__device__ float  g_skip[(size_t)100000 * HC];   // skip fp32, streamed
__device__ float  g_acc[(size_t)100000 * HC];
__device__ float  g_denom[(size_t)100000 * 2];

__device__ __forceinline__ void red2(float* p, float a, float b) {
    asm volatile("red.global.add.v2.f32 [%0], {%1, %2};" :: "l"(p), "f"(a), "f"(b) : "memory");
}
__device__ __forceinline__ void red4(float* p, float a, float b, float c, float d) {
    asm volatile("red.global.add.v4.f32 [%0], {%1, %2, %3, %4};"
                 :: "l"(p), "f"(a), "f"(b), "f"(c), "f"(d) : "memory");
}
__device__ __forceinline__ void prefetchL2(const void* p) {
    asm volatile("prefetch.global.L2 [%0];" :: "l"(p));
}
__device__ __forceinline__ uint32_t smem_u32(const void* p) {
    uint32_t a;
    asm("{ .reg .u64 t; cvta.to.shared.u64 t, %1; cvt.u32.u64 %0, t; }" : "=r"(a) : "l"(p));
    return a;
}
__device__ __forceinline__ void ldsm_x4(uint32_t* r, uint32_t a) {
    asm volatile("ldmatrix.sync.aligned.m8n8.x4.shared.b16 {%0,%1,%2,%3}, [%4];"
                 : "=r"(r[0]), "=r"(r[1]), "=r"(r[2]), "=r"(r[3]) : "r"(a));
}
__device__ __forceinline__ void ldsm_x2(uint32_t* r, uint32_t a) {
    asm volatile("ldmatrix.sync.aligned.m8n8.x2.shared.b16 {%0,%1}, [%2];"
                 : "=r"(r[0]), "=r"(r[1]) : "r"(a));
}
__device__ __forceinline__ void mma16816(float* c, const uint32_t* a, const uint32_t* b) {
    asm volatile("mma.sync.aligned.m16n8k16.row.col.f32.f16.f16.f32 "
                 "{%0,%1,%2,%3}, {%4,%5,%6,%7}, {%8,%9}, {%0,%1,%2,%3};"
                 : "+f"(c[0]), "+f"(c[1]), "+f"(c[2]), "+f"(c[3])
                 : "r"(a[0]), "r"(a[1]), "r"(a[2]), "r"(a[3]), "r"(b[0]), "r"(b[1]));
}
__device__ __forceinline__ float4 h4_to_f4(uint2 u) {
    __half2* ph = reinterpret_cast<__half2*>(&u);
    float2 a = __half22float2(ph[0]);
    float2 b = __half22float2(ph[1]);
    return make_float4(a.x, a.y, b.x, b.y);
}

// ---------------------------------------------------------------------------
// Node projections: HMMA fp16 (R13). q|k|v fp16, skip fp32. Zeroes acc/denom.
// ---------------------------------------------------------------------------
#define NP_W   0
#define NP_B   96000
#define NP_A   97600
#define SMEM_NP_BYTES 112960
#define NPSTR  240

__global__ void __launch_bounds__(256, 2) k_nproj(
    const float* __restrict__ x,
    const float* __restrict__ Wq, const float* __restrict__ bq,
    const float* __restrict__ Wk, const float* __restrict__ bk,
    const float* __restrict__ Wv, const float* __restrict__ bv,
    const float* __restrict__ Ws, const float* __restrict__ bs,
    int n)
{
    extern __shared__ char smb[];
    uint32_t sbase = smem_u32(smb);
    int tid = threadIdx.x;
    int warp = tid >> 5, lane = tid & 31;
    int gtid = blockIdx.x * 256 + tid;
    int gstep = gridDim.x * 256;

    {
        int na = n * 25;
        int tot = na + n;
        float4 z4 = make_float4(0.f, 0.f, 0.f, 0.f);
        for (int i = gtid; i < tot; i += gstep) {
            if (i < na) ((float4*)g_acc)[i] = z4;
            else        ((float2*)g_denom)[i - na] = make_float2(0.f, 0.f);
        }
    }

    for (int idx = tid; idx < 400 * 100; idx += 256) {
        int c = idx / 100, j = idx - c * 100;
        float v;
        if      (c < 100) v = Wq[j * 100 + c];
        else if (c < 200) v = Wk[j * 100 + c - 100];
        else if (c < 300) v = Wv[j * 100 + c - 200];
        else              v = Ws[j * 100 + c - 300];
        *(__half*)(smb + NP_W + c * NPSTR + j * 2) = __float2half_rn(v);
    }
    for (int idx = tid; idx < 400 * 10; idx += 256) {
        int c = idx / 10, z = idx - c * 10;
        *(uint32_t*)(smb + NP_W + c * NPSTR + 200 + z * 4) = 0u;
    }
    {
        float* bsm = (float*)(smb + NP_B);
        for (int i = tid; i < 400; i += 256) {
            bsm[i] = (i < 100) ? bq[i] : (i < 200) ? bk[i - 100]
                   : (i < 300) ? bv[i - 200] : bs[i - 300];
        }
    }
    __syncthreads();

    const float* bsm = (const float*)(smb + NP_B);
    int mrow = (warp & 3) * 16;
    int nfbase = (warp >> 2) * 25;

    int ntiles = (n + 63) >> 6;
    for (int tile = blockIdx.x; tile < ntiles; tile += gridDim.x) {
        int nbase = tile << 6;
        __syncthreads();

        for (int idx = tid; idx < 64 * 25; idx += 256) {
            int r = idx / 25, q = idx - r * 25;
            int nd = nbase + r; if (nd >= n) nd = n - 1;
            float4 v = ((const float4*)(x + (size_t)nd * 100))[q];
            __half2 h0, h1;
            h0.x = __float2half_rn(v.x); h0.y = __float2half_rn(v.y);
            h1.x = __float2half_rn(v.z); h1.y = __float2half_rn(v.w);
            uint2 p;
            p.x = *reinterpret_cast<uint32_t*>(&h0);
            p.y = *reinterpret_cast<uint32_t*>(&h1);
            *(uint2*)(smb + NP_A + r * NPSTR + q * 8) = p;
        }
        for (int idx = tid; idx < 64 * 10; idx += 256) {
            int r = idx / 10, z = idx - r * 10;
            *(uint32_t*)(smb + NP_A + r * NPSTR + 200 + z * 4) = 0u;
        }
        __syncthreads();

        uint32_t abase = sbase + NP_A
                       + (uint32_t)((mrow + (lane & 15)) * NPSTR + (lane >> 4) * 16);
        uint32_t af[7][4];
        #pragma unroll
        for (int k = 0; k < 7; k++) ldsm_x4(af[k], abase + k * 32);

        int rowA = mrow + (lane >> 2);
        int nd0 = nbase + rowA;
        int nd1 = nd0 + 8;

        #pragma unroll 1
        for (int nf = 0; nf < 25; nf++) {
            int nfg = nfbase + nf;
            uint32_t bb = sbase + NP_W
                + (uint32_t)((nfg * 8 + (lane & 7)) * NPSTR + (lane >> 3) * 16);
            float ac[4] = {0.f, 0.f, 0.f, 0.f};
            #pragma unroll
            for (int kk = 0; kk < 3; kk++) {
                uint32_t bh[4];
                ldsm_x4(bh, bb + kk * 64);
                mma16816(ac, af[2 * kk],     bh);
                mma16816(ac, af[2 * kk + 1], bh + 2);
            }
            uint32_t b2[2];
            ldsm_x2(b2, bb + 192);
            mma16816(ac, af[6], b2);

            int col = nfg * 8 + 2 * (lane & 3);
            float bx = bsm[col], by = bsm[col + 1];
            if (col < 300) {
                __half2 h0, h1;
                h0.x = __float2half_rn(ac[0] + bx); h0.y = __float2half_rn(ac[1] + by);
                h1.x = __float2half_rn(ac[2] + bx); h1.y = __float2half_rn(ac[3] + by);
                if (nd0 < n) *(__half2*)(g_qkv + (size_t)nd0 * 300 + col) = h0;
                if (nd1 < n) *(__half2*)(g_qkv + (size_t)nd1 * 300 + col) = h1;
            } else {
                int sc = col - 300;
                if (nd0 < n)
                    *(float2*)(g_skip + (size_t)nd0 * 100 + sc) =
                        make_float2(ac[0] + bx, ac[1] + by);
                if (nd1 < n)
                    *(float2*)(g_skip + (size_t)nd1 * 100 + sc) =
                        make_float2(ac[2] + bx, ac[3] + by);
            }
        }
    }
}

// ---------------------------------------------------------------------------
// Edge kernel: ETILE=96, 384 threads, 2 CTAs/SM (24 warps/SM).
// k-outer MMA loop (low regs), warp = m16 x n-half (6M x 2N).
// ---------------------------------------------------------------------------
#define SM_W    0
#define SM_A    58240
#define SM_SRC  112000
#define SM_DST  112384
#define SM_REL  112768
#define SM_WTB  113152
#define SMEM_EDGE_BYTES 113952
#define ETILE 96
#define ESTR  108

__device__ __forceinline__ void build_tile(
    char* smb, const float* __restrict__ msg, int ebase, int ne, int tid)
{
    const float* wtb = (const float*)(smb + SM_WTB);
    const float* rel = (const float*)(smb + SM_REL);
    for (int idx = tid; idx < ETILE * 34; idx += 384) {
        int r = idx / 34, g = idx - r * 34;
        int j0 = g * 8;
        int eg = ebase + r; if (eg >= ne) eg = ne - 1;
        float v[8];
        if (j0 + 8 <= 100) {
            float rr = rel[r];
            #pragma unroll
            for (int i = 0; i < 8; i++)
                v[i] = __cosf(fmaf(rr, wtb[j0 + i], wtb[100 + j0 + i]));
        } else if (j0 >= 104) {
            const float4* m4 = (const float4*)(msg + (size_t)eg * 172 + (j0 - 100));
            float4 a = m4[0], b = m4[1];
            v[0] = a.x; v[1] = a.y; v[2] = a.z; v[3] = a.w;
            v[4] = b.x; v[5] = b.y; v[6] = b.z; v[7] = b.w;
        } else {
            float rr = rel[r];
            const float* mrow = msg + (size_t)eg * 172;
            #pragma unroll
            for (int i = 0; i < 8; i++) {
                int j = j0 + i;
                v[i] = (j < 100) ? __cosf(fmaf(rr, wtb[j], wtb[100 + j])) : mrow[j - 100];
            }
        }
        uint32_t p[4];
        #pragma unroll
        for (int i = 0; i < 4; i++) {
            __half2 h;
            h.x = __float2half_rn(v[2 * i]);
            h.y = __float2half_rn(v[2 * i + 1]);
            p[i] = *reinterpret_cast<uint32_t*>(&h);
        }
        *(uint4*)(smb + SM_A + r * 560 + j0 * 2) = make_uint4(p[0], p[1], p[2], p[3]);
    }
}

__global__ void __launch_bounds__(384, 2) k_edge(
    const float* __restrict__ lu, const float* __restrict__ t,
    const float* __restrict__ msg,
    const float* __restrict__ Wt, const float* __restrict__ bt,
    const float* __restrict__ We, const int* __restrict__ ei,
    int n, int ne)
{
    extern __shared__ char smb[];
    uint32_t sbase = smem_u32(smb);
    int tid = threadIdx.x;
    int warp = tid >> 5, lane = tid & 31;

    for (int idx = tid; idx < 104 * 272; idx += 384) {
        int c = idx / 272, j = idx - c * 272;
        float w = (c < 100) ? We[j * 100 + c] : 0.0f;
        *(__half*)(smb + SM_W + c * 560 + j * 2) = __float2half_rn(w);
    }
    {
        float* wtb = (float*)(smb + SM_WTB);
        for (int i = tid; i < 100; i += 384) { wtb[i] = Wt[i]; wtb[100 + i] = bt[i]; }
    }
    __syncthreads();

    int* s_src = (int*)(smb + SM_SRC);
    int* s_dst = (int*)(smb + SM_DST);
    float* s_rel = (float*)(smb + SM_REL);
    float* es = (float*)(smb + SM_A);
    const float SCALE = 0.14142135623730951f;
    int lq = (lane < 25) ? lane : 24;

    // warp role: mblock = warp % 6, n-half = warp / 6
    int mrow = (warp % 6) * 16;
    int nh   = warp / 6;
    int nf0  = nh * 7;
    int nfe  = nh ? 13 : 7;

    int ntiles = (ne + ETILE - 1) / ETILE;
    for (int tile = blockIdx.x; tile < ntiles; tile += gridDim.x) {
        int ebase = tile * ETILE;
        __syncthreads();

        if (tid < ETILE) {
            int eg = ebase + tid;
            bool valid = eg < ne;
            int eidx = valid ? eg : 0;
            int s = ei[eidx], d = ei[ne + eidx];
            s_src[tid] = s; s_dst[tid] = d;
            s_rel[tid] = valid ? (lu[s] - t[eidx]) : 0.0f;
            if (valid) {
                const char* qb = (const char*)(g_qkv + (size_t)d * 300);
                const char* kb = (const char*)(g_qkv + (size_t)s * 300 + 100);
                prefetchL2(qb); prefetchL2(qb + 128);
                prefetchL2(kb); prefetchL2(kb + 128);
                prefetchL2(kb + 256); prefetchL2(kb + 384);
            }
        }
        __syncthreads();

        build_tile(smb, msg, ebase, ne, tid);
        __syncthreads();

        float acc[7][4];
        #pragma unroll
        for (int j = 0; j < 7; j++) {
            acc[j][0] = 0.f; acc[j][1] = 0.f; acc[j][2] = 0.f; acc[j][3] = 0.f;
        }

        {
            uint32_t abase = sbase + SM_A
                           + (uint32_t)((mrow + (lane & 15)) * 560 + (lane >> 4) * 16);
            uint32_t brow = sbase + SM_W
                          + (uint32_t)((nf0 * 8 + (lane & 7)) * 560 + ((lane >> 3) & 1) * 16);
            int nnf = nfe - nf0;   // 7 or 6
            #pragma unroll 1
            for (int k = 0; k < 17; k++) {
                uint32_t afk[4];
                ldsm_x4(afk, abase + k * 32);
                uint32_t bk = brow + k * 32;
                #pragma unroll
                for (int j = 0; j < 7; j++) {
                    if (j < nnf) {
                        uint32_t b2[2];
                        ldsm_x2(b2, bk + j * (8 * 560));
                        mma16816(acc[j], afk, b2);
                    }
                }
            }
        }
        __syncthreads();

        {
            int rowA = mrow + (lane >> 2);
            #pragma unroll
            for (int j = 0; j < 7; j++) {
                int nf = nf0 + j;
                if (nf < nfe) {
                    int col = nf * 8 + 2 * (lane & 3);
                    *(float2*)(es + rowA * ESTR + col)       = make_float2(acc[j][0], acc[j][1]);
                    *(float2*)(es + (rowA + 8) * ESTR + col) = make_float2(acc[j][2], acc[j][3]);
                }
            }
        }
        __syncthreads();

        // 2-edge interleaved epilogue: warp owns edges [warp*8, warp*8+8)
        #pragma unroll 1
        for (int i = 0; i < 8; i += 2) {
            int er0 = warp * 8 + i;
            int er1 = er0 + 1;
            int eg0 = ebase + er0;
            if (eg0 >= ne) break;
            bool v1 = (ebase + er1) < ne;
            int s0 = s_src[er0], d0 = s_dst[er0];
            int s1 = s_src[er1], d1 = s_dst[er1];
            float4 e40 = make_float4(0,0,0,0), e41 = e40;
            float4 q0 = e40, k0 = e40, vv0 = e40;
            float4 q1 = e40, k1 = e40, vv1 = e40;
            float d00 = 0.f, d01 = 0.f, d10 = 0.f, d11 = 0.f;
            if (lane < 25) {
                e40 = *(const float4*)(es + er0 * ESTR + lq * 4);
                e41 = *(const float4*)(es + er1 * ESTR + lq * 4);
                q0  = h4_to_f4(*(const uint2*)(g_qkv + (size_t)d0 * 300 + lq * 4));
                q1  = h4_to_f4(*(const uint2*)(g_qkv + (size_t)d1 * 300 + lq * 4));
                k0  = h4_to_f4(*(const uint2*)(g_qkv + (size_t)s0 * 300 + 100 + lq * 4));
                k1  = h4_to_f4(*(const uint2*)(g_qkv + (size_t)s1 * 300 + 100 + lq * 4));
                vv0 = h4_to_f4(*(const uint2*)(g_qkv + (size_t)s0 * 300 + 200 + lq * 4));
                vv1 = h4_to_f4(*(const uint2*)(g_qkv + (size_t)s1 * 300 + 200 + lq * 4));
                d00 = q0.x * (k0.x + e40.x) + q0.y * (k0.y + e40.y);
                d01 = q0.z * (k0.z + e40.z) + q0.w * (k0.w + e40.w);
                d10 = q1.x * (k1.x + e41.x) + q1.y * (k1.y + e41.y);
                d11 = q1.z * (k1.z + e41.z) + q1.w * (k1.w + e41.w);
            }
            float p00 = ((lane < 13) ? d00 : 0.0f) + ((lane < 12) ? d01 : 0.0f);
            float p01 = ((lane < 13) ? 0.0f : d00) + ((lane < 12) ? 0.0f : d01);
            float p10 = ((lane < 13) ? d10 : 0.0f) + ((lane < 12) ? d11 : 0.0f);
            float p11 = ((lane < 13) ? 0.0f : d10) + ((lane < 12) ? 0.0f : d11);
            #pragma unroll
            for (int o = 16; o > 0; o >>= 1) {
                p00 += __shfl_xor_sync(0xffffffffu, p00, o);
                p01 += __shfl_xor_sync(0xffffffffu, p01, o);
                p10 += __shfl_xor_sync(0xffffffffu, p10, o);
                p11 += __shfl_xor_sync(0xffffffffu, p11, o);
            }
            float ex00 = __expf(p00 * SCALE), ex01 = __expf(p01 * SCALE);
            float ex10 = __expf(p10 * SCALE), ex11 = __expf(p11 * SCALE);
            if (lane == 0) red2(&g_denom[(size_t)d0 * 2], ex00, ex01);
            if (lane == 1 && v1) red2(&g_denom[(size_t)d1 * 2], ex10, ex11);
            if (lane < 25) {
                float w00 = (lane < 13) ? ex00 : ex01;
                float w01 = (lane < 12) ? ex00 : ex01;
                red4(g_acc + (size_t)d0 * 100 + lq * 4,
                     w00 * (vv0.x + e40.x), w00 * (vv0.y + e40.y),
                     w01 * (vv0.z + e40.z), w01 * (vv0.w + e40.w));
                if (v1) {
                    float w10 = (lane < 13) ? ex10 : ex11;
                    float w11 = (lane < 12) ? ex10 : ex11;
                    red4(g_acc + (size_t)d1 * 100 + lq * 4,
                         w10 * (vv1.x + e41.x), w10 * (vv1.y + e41.y),
                         w11 * (vv1.z + e41.z), w11 * (vv1.w + e41.w));
                }
            }
        }
    }
}

// ---------------------------------------------------------------------------
__global__ void k_final(float* __restrict__ out, int n) {
    int tot = n * 25;
    for (int i = blockIdx.x * blockDim.x + threadIdx.x; i < tot;
         i += gridDim.x * blockDim.x) {
        int nd = i / 25, q = i % 25;
        float den0 = g_denom[(size_t)nd * 2 + 0];
        float den1 = g_denom[(size_t)nd * 2 + 1];
        float dxy = (q < 13) ? den0 : den1;
        float dzw = (q < 12) ? den0 : den1;
        float rxy = (dxy > 0.0f) ? (1.0f / dxy) : 0.0f;
        float rzw = (dzw > 0.0f) ? (1.0f / dzw) : 0.0f;
        float4 a4 = ((const float4*)g_acc)[i];
        float4 sk = ((const float4*)g_skip)[i];
        float4 o;
        o.x = a4.x * rxy + sk.x;
        o.y = a4.y * rxy + sk.y;
        o.z = a4.z * rzw + sk.z;
        o.w = a4.w * rzw + sk.w;
        ((float4*)out)[i] = o;
    }
}

// ---------------------------------------------------------------------------
extern "C" void kernel_launch(void* const* d_in, const int* in_sizes, int n_in,
                              void* d_out, int out_size) {
    const float* x   = (const float*)d_in[0];
    const float* lu  = (const float*)d_in[1];
    const float* t   = (const float*)d_in[2];
    const float* msg = (const float*)d_in[3];
    const float* Wt  = (const float*)d_in[4];
    const float* bt  = (const float*)d_in[5];
    const float* Wq  = (const float*)d_in[6];
    const float* bq  = (const float*)d_in[7];
    const float* Wk  = (const float*)d_in[8];
    const float* bk  = (const float*)d_in[9];
    const float* Wv  = (const float*)d_in[10];
    const float* bv  = (const float*)d_in[11];
    const float* We  = (const float*)d_in[12];
    const float* Ws  = (const float*)d_in[13];
    const float* bs  = (const float*)d_in[14];
    const int*   ei  = (const int*)d_in[15];

    int n  = in_sizes[1];
    int ne = in_sizes[2];
    float* out = (float*)d_out;

    int dev = 0;
    cudaGetDevice(&dev);
    int nsm = 148;
    cudaDeviceGetAttribute(&nsm, cudaDevAttrMultiProcessorCount, dev);

    cudaFuncSetAttribute(k_nproj, cudaFuncAttributeMaxDynamicSharedMemorySize, SMEM_NP_BYTES);
    cudaFuncSetAttribute(k_edge,  cudaFuncAttributeMaxDynamicSharedMemorySize, SMEM_EDGE_BYTES);

    k_nproj<<<nsm * 2, 256, SMEM_NP_BYTES>>>(x, Wq, bq, Wk, bk, Wv, bv, Ws, bs, n);
    k_edge<<<nsm * 2, 384, SMEM_EDGE_BYTES>>>(lu, t, msg, Wt, bt, We, ei, n, ne);
    k_final<<<4096, 256>>>(out, n);
}

// round 17
// speedup vs baseline: 1.7193x; 1.0123x over previous
#include <cuda_runtime.h>
#include <cuda_fp16.h>
#include <cstdint>

#define HC 100
typedef unsigned long long ull;

__device__ __half g_qkv[(size_t)100000 * 300];   // q|k|v fp16, gathered
__device__ float  g_skip[(size_t)100000 * HC];   // skip fp32, streamed
__device__ float  g_acc[(size_t)100000 * HC];
__device__ float  g_denom[(size_t)100000 * 2];

__device__ __forceinline__ void red2(float* p, float a, float b) {
    asm volatile("red.global.add.v2.f32 [%0], {%1, %2};" :: "l"(p), "f"(a), "f"(b) : "memory");
}
__device__ __forceinline__ void red4(float* p, float a, float b, float c, float d) {
    asm volatile("red.global.add.v4.f32 [%0], {%1, %2, %3, %4};"
                 :: "l"(p), "f"(a), "f"(b), "f"(c), "f"(d) : "memory");
}
__device__ __forceinline__ void prefetchL2(const void* p) {
    asm volatile("prefetch.global.L2 [%0];" :: "l"(p));
}
__device__ __forceinline__ uint32_t smem_u32(const void* p) {
    uint32_t a;
    asm("{ .reg .u64 t; cvta.to.shared.u64 t, %1; cvt.u32.u64 %0, t; }" : "=r"(a) : "l"(p));
    return a;
}
__device__ __forceinline__ void ldsm_x4(uint32_t* r, uint32_t a) {
    asm volatile("ldmatrix.sync.aligned.m8n8.x4.shared.b16 {%0,%1,%2,%3}, [%4];"
                 : "=r"(r[0]), "=r"(r[1]), "=r"(r[2]), "=r"(r[3]) : "r"(a));
}
__device__ __forceinline__ void ldsm_x2(uint32_t* r, uint32_t a) {
    asm volatile("ldmatrix.sync.aligned.m8n8.x2.shared.b16 {%0,%1}, [%2];"
                 : "=r"(r[0]), "=r"(r[1]) : "r"(a));
}
__device__ __forceinline__ void mma16816(float* c, const uint32_t* a, const uint32_t* b) {
    asm volatile("mma.sync.aligned.m16n8k16.row.col.f32.f16.f16.f32 "
                 "{%0,%1,%2,%3}, {%4,%5,%6,%7}, {%8,%9}, {%0,%1,%2,%3};"
                 : "+f"(c[0]), "+f"(c[1]), "+f"(c[2]), "+f"(c[3])
                 : "r"(a[0]), "r"(a[1]), "r"(a[2]), "r"(a[3]), "r"(b[0]), "r"(b[1]));
}
__device__ __forceinline__ float4 h4_to_f4(uint2 u) {
    __half2* ph = reinterpret_cast<__half2*>(&u);
    float2 a = __half22float2(ph[0]);
    float2 b = __half22float2(ph[1]);
    return make_float4(a.x, a.y, b.x, b.y);
}

// ---------------------------------------------------------------------------
// Node projections: HMMA fp16, 512 threads (16 warps), 2 CTAs/SM (32 warps/SM).
// Warp = mblock(4) x nf-quarter(4); A-fragments streamed (low regs).
// Also zeroes g_acc/g_denom.
// ---------------------------------------------------------------------------
#define NP_W   0
#define NP_B   96000
#define NP_A   97600
#define SMEM_NP_BYTES 112960
#define NPSTR  240

__global__ void __launch_bounds__(512, 2) k_nproj(
    const float* __restrict__ x,
    const float* __restrict__ Wq, const float* __restrict__ bq,
    const float* __restrict__ Wk, const float* __restrict__ bk,
    const float* __restrict__ Wv, const float* __restrict__ bv,
    const float* __restrict__ Ws, const float* __restrict__ bs,
    int n)
{
    extern __shared__ char smb[];
    uint32_t sbase = smem_u32(smb);
    int tid = threadIdx.x;
    int warp = tid >> 5, lane = tid & 31;
    int gtid = blockIdx.x * 512 + tid;
    int gstep = gridDim.x * 512;

    {
        int na = n * 25;
        int tot = na + n;
        float4 z4 = make_float4(0.f, 0.f, 0.f, 0.f);
        for (int i = gtid; i < tot; i += gstep) {
            if (i < na) ((float4*)g_acc)[i] = z4;
            else        ((float2*)g_denom)[i - na] = make_float2(0.f, 0.f);
        }
    }

    for (int idx = tid; idx < 400 * 100; idx += 512) {
        int c = idx / 100, j = idx - c * 100;
        float v;
        if      (c < 100) v = Wq[j * 100 + c];
        else if (c < 200) v = Wk[j * 100 + c - 100];
        else if (c < 300) v = Wv[j * 100 + c - 200];
        else              v = Ws[j * 100 + c - 300];
        *(__half*)(smb + NP_W + c * NPSTR + j * 2) = __float2half_rn(v);
    }
    for (int idx = tid; idx < 400 * 10; idx += 512) {
        int c = idx / 10, z = idx - c * 10;
        *(uint32_t*)(smb + NP_W + c * NPSTR + 200 + z * 4) = 0u;
    }
    {
        float* bsm = (float*)(smb + NP_B);
        for (int i = tid; i < 400; i += 512) {
            bsm[i] = (i < 100) ? bq[i] : (i < 200) ? bk[i - 100]
                   : (i < 300) ? bv[i - 200] : bs[i - 300];
        }
    }
    __syncthreads();

    const float* bsm = (const float*)(smb + NP_B);
    int mrow = (warp & 3) * 16;
    int nfq  = warp >> 2;                       // 0..3
    int nf0  = nfq * 13;
    int nfe  = (nf0 + 13 < 50) ? (nf0 + 13) : 50;

    int ntiles = (n + 63) >> 6;
    for (int tile = blockIdx.x; tile < ntiles; tile += gridDim.x) {
        int nbase = tile << 6;
        __syncthreads();

        for (int idx = tid; idx < 64 * 25; idx += 512) {
            int r = idx / 25, q = idx - r * 25;
            int nd = nbase + r; if (nd >= n) nd = n - 1;
            float4 v = ((const float4*)(x + (size_t)nd * 100))[q];
            __half2 h0, h1;
            h0.x = __float2half_rn(v.x); h0.y = __float2half_rn(v.y);
            h1.x = __float2half_rn(v.z); h1.y = __float2half_rn(v.w);
            uint2 p;
            p.x = *reinterpret_cast<uint32_t*>(&h0);
            p.y = *reinterpret_cast<uint32_t*>(&h1);
            *(uint2*)(smb + NP_A + r * NPSTR + q * 8) = p;
        }
        for (int idx = tid; idx < 64 * 10; idx += 512) {
            int r = idx / 10, z = idx - r * 10;
            *(uint32_t*)(smb + NP_A + r * NPSTR + 200 + z * 4) = 0u;
        }
        __syncthreads();

        uint32_t abase = sbase + NP_A
                       + (uint32_t)((mrow + (lane & 15)) * NPSTR + (lane >> 4) * 16);
        int rowA = mrow + (lane >> 2);
        int nd0 = nbase + rowA;
        int nd1 = nd0 + 8;

        #pragma unroll 1
        for (int nfg = nf0; nfg < nfe; nfg++) {
            uint32_t bb = sbase + NP_W
                + (uint32_t)((nfg * 8 + (lane & 7)) * NPSTR + (lane >> 3) * 16);
            float ac[4] = {0.f, 0.f, 0.f, 0.f};
            #pragma unroll
            for (int kk = 0; kk < 3; kk++) {
                uint32_t afa[4], afb[4], bh[4];
                ldsm_x4(afa, abase + (2 * kk) * 32);
                ldsm_x4(afb, abase + (2 * kk + 1) * 32);
                ldsm_x4(bh, bb + kk * 64);
                mma16816(ac, afa, bh);
                mma16816(ac, afb, bh + 2);
            }
            {
                uint32_t af6[4], b2[2];
                ldsm_x4(af6, abase + 6 * 32);
                ldsm_x2(b2, bb + 192);
                mma16816(ac, af6, b2);
            }

            int col = nfg * 8 + 2 * (lane & 3);
            float bx = bsm[col], by = bsm[col + 1];
            if (col < 300) {
                __half2 h0, h1;
                h0.x = __float2half_rn(ac[0] + bx); h0.y = __float2half_rn(ac[1] + by);
                h1.x = __float2half_rn(ac[2] + bx); h1.y = __float2half_rn(ac[3] + by);
                if (nd0 < n) *(__half2*)(g_qkv + (size_t)nd0 * 300 + col) = h0;
                if (nd1 < n) *(__half2*)(g_qkv + (size_t)nd1 * 300 + col) = h1;
            } else {
                int sc = col - 300;
                if (nd0 < n)
                    *(float2*)(g_skip + (size_t)nd0 * 100 + sc) =
                        make_float2(ac[0] + bx, ac[1] + by);
                if (nd1 < n)
                    *(float2*)(g_skip + (size_t)nd1 * 100 + sc) =
                        make_float2(ac[2] + bx, ac[3] + by);
            }
        }
    }
}

// ---------------------------------------------------------------------------
// Edge kernel (R16): ETILE=96, 384 threads, 2 CTAs/SM (24 warps/SM).
// ---------------------------------------------------------------------------
#define SM_W    0
#define SM_A    58240
#define SM_SRC  112000
#define SM_DST  112384
#define SM_REL  112768
#define SM_WTB  113152
#define SMEM_EDGE_BYTES 113952
#define ETILE 96
#define ESTR  108

__device__ __forceinline__ void build_tile(
    char* smb, const float* __restrict__ msg, int ebase, int ne, int tid)
{
    const float* wtb = (const float*)(smb + SM_WTB);
    const float* rel = (const float*)(smb + SM_REL);
    for (int idx = tid; idx < ETILE * 34; idx += 384) {
        int r = idx / 34, g = idx - r * 34;
        int j0 = g * 8;
        int eg = ebase + r; if (eg >= ne) eg = ne - 1;
        float v[8];
        if (j0 + 8 <= 100) {
            float rr = rel[r];
            #pragma unroll
            for (int i = 0; i < 8; i++)
                v[i] = __cosf(fmaf(rr, wtb[j0 + i], wtb[100 + j0 + i]));
        } else if (j0 >= 104) {
            const float4* m4 = (const float4*)(msg + (size_t)eg * 172 + (j0 - 100));
            float4 a = m4[0], b = m4[1];
            v[0] = a.x; v[1] = a.y; v[2] = a.z; v[3] = a.w;
            v[4] = b.x; v[5] = b.y; v[6] = b.z; v[7] = b.w;
        } else {
            float rr = rel[r];
            const float* mrow = msg + (size_t)eg * 172;
            #pragma unroll
            for (int i = 0; i < 8; i++) {
                int j = j0 + i;
                v[i] = (j < 100) ? __cosf(fmaf(rr, wtb[j], wtb[100 + j])) : mrow[j - 100];
            }
        }
        uint32_t p[4];
        #pragma unroll
        for (int i = 0; i < 4; i++) {
            __half2 h;
            h.x = __float2half_rn(v[2 * i]);
            h.y = __float2half_rn(v[2 * i + 1]);
            p[i] = *reinterpret_cast<uint32_t*>(&h);
        }
        *(uint4*)(smb + SM_A + r * 560 + j0 * 2) = make_uint4(p[0], p[1], p[2], p[3]);
    }
}

__global__ void __launch_bounds__(384, 2) k_edge(
    const float* __restrict__ lu, const float* __restrict__ t,
    const float* __restrict__ msg,
    const float* __restrict__ Wt, const float* __restrict__ bt,
    const float* __restrict__ We, const int* __restrict__ ei,
    int n, int ne)
{
    extern __shared__ char smb[];
    uint32_t sbase = smem_u32(smb);
    int tid = threadIdx.x;
    int warp = tid >> 5, lane = tid & 31;

    for (int idx = tid; idx < 104 * 272; idx += 384) {
        int c = idx / 272, j = idx - c * 272;
        float w = (c < 100) ? We[j * 100 + c] : 0.0f;
        *(__half*)(smb + SM_W + c * 560 + j * 2) = __float2half_rn(w);
    }
    {
        float* wtb = (float*)(smb + SM_WTB);
        for (int i = tid; i < 100; i += 384) { wtb[i] = Wt[i]; wtb[100 + i] = bt[i]; }
    }
    __syncthreads();

    int* s_src = (int*)(smb + SM_SRC);
    int* s_dst = (int*)(smb + SM_DST);
    float* s_rel = (float*)(smb + SM_REL);
    float* es = (float*)(smb + SM_A);
    const float SCALE = 0.14142135623730951f;
    int lq = (lane < 25) ? lane : 24;

    int mrow = (warp % 6) * 16;
    int nh   = warp / 6;
    int nf0  = nh * 7;
    int nfe  = nh ? 13 : 7;

    int ntiles = (ne + ETILE - 1) / ETILE;
    for (int tile = blockIdx.x; tile < ntiles; tile += gridDim.x) {
        int ebase = tile * ETILE;
        __syncthreads();

        if (tid < ETILE) {
            int eg = ebase + tid;
            bool valid = eg < ne;
            int eidx = valid ? eg : 0;
            int s = ei[eidx], d = ei[ne + eidx];
            s_src[tid] = s; s_dst[tid] = d;
            s_rel[tid] = valid ? (lu[s] - t[eidx]) : 0.0f;
            if (valid) {
                const char* qb = (const char*)(g_qkv + (size_t)d * 300);
                const char* kb = (const char*)(g_qkv + (size_t)s * 300 + 100);
                prefetchL2(qb); prefetchL2(qb + 128);
                prefetchL2(kb); prefetchL2(kb + 128);
                prefetchL2(kb + 256); prefetchL2(kb + 384);
            }
        }
        __syncthreads();

        build_tile(smb, msg, ebase, ne, tid);
        __syncthreads();

        float acc[7][4];
        #pragma unroll
        for (int j = 0; j < 7; j++) {
            acc[j][0] = 0.f; acc[j][1] = 0.f; acc[j][2] = 0.f; acc[j][3] = 0.f;
        }

        {
            uint32_t abase = sbase + SM_A
                           + (uint32_t)((mrow + (lane & 15)) * 560 + (lane >> 4) * 16);
            uint32_t brow = sbase + SM_W
                          + (uint32_t)((nf0 * 8 + (lane & 7)) * 560 + ((lane >> 3) & 1) * 16);
            int nnf = nfe - nf0;
            #pragma unroll 1
            for (int k = 0; k < 17; k++) {
                uint32_t afk[4];
                ldsm_x4(afk, abase + k * 32);
                uint32_t bk = brow + k * 32;
                #pragma unroll
                for (int j = 0; j < 7; j++) {
                    if (j < nnf) {
                        uint32_t b2[2];
                        ldsm_x2(b2, bk + j * (8 * 560));
                        mma16816(acc[j], afk, b2);
                    }
                }
            }
        }
        __syncthreads();

        {
            int rowA = mrow + (lane >> 2);
            #pragma unroll
            for (int j = 0; j < 7; j++) {
                int nf = nf0 + j;
                if (nf < nfe) {
                    int col = nf * 8 + 2 * (lane & 3);
                    *(float2*)(es + rowA * ESTR + col)       = make_float2(acc[j][0], acc[j][1]);
                    *(float2*)(es + (rowA + 8) * ESTR + col) = make_float2(acc[j][2], acc[j][3]);
                }
            }
        }
        __syncthreads();

        #pragma unroll 1
        for (int i = 0; i < 8; i += 2) {
            int er0 = warp * 8 + i;
            int er1 = er0 + 1;
            int eg0 = ebase + er0;
            if (eg0 >= ne) break;
            bool v1 = (ebase + er1) < ne;
            int s0 = s_src[er0], d0 = s_dst[er0];
            int s1 = s_src[er1], d1 = s_dst[er1];
            float4 e40 = make_float4(0,0,0,0), e41 = e40;
            float4 q0 = e40, k0 = e40, vv0 = e40;
            float4 q1 = e40, k1 = e40, vv1 = e40;
            float d00 = 0.f, d01 = 0.f, d10 = 0.f, d11 = 0.f;
            if (lane < 25) {
                e40 = *(const float4*)(es + er0 * ESTR + lq * 4);
                e41 = *(const float4*)(es + er1 * ESTR + lq * 4);
                q0  = h4_to_f4(*(const uint2*)(g_qkv + (size_t)d0 * 300 + lq * 4));
                q1  = h4_to_f4(*(const uint2*)(g_qkv + (size_t)d1 * 300 + lq * 4));
                k0  = h4_to_f4(*(const uint2*)(g_qkv + (size_t)s0 * 300 + 100 + lq * 4));
                k1  = h4_to_f4(*(const uint2*)(g_qkv + (size_t)s1 * 300 + 100 + lq * 4));
                vv0 = h4_to_f4(*(const uint2*)(g_qkv + (size_t)s0 * 300 + 200 + lq * 4));
                vv1 = h4_to_f4(*(const uint2*)(g_qkv + (size_t)s1 * 300 + 200 + lq * 4));
                d00 = q0.x * (k0.x + e40.x) + q0.y * (k0.y + e40.y);
                d01 = q0.z * (k0.z + e40.z) + q0.w * (k0.w + e40.w);
                d10 = q1.x * (k1.x + e41.x) + q1.y * (k1.y + e41.y);
                d11 = q1.z * (k1.z + e41.z) + q1.w * (k1.w + e41.w);
            }
            float p00 = ((lane < 13) ? d00 : 0.0f) + ((lane < 12) ? d01 : 0.0f);
            float p01 = ((lane < 13) ? 0.0f : d00) + ((lane < 12) ? 0.0f : d01);
            float p10 = ((lane < 13) ? d10 : 0.0f) + ((lane < 12) ? d11 : 0.0f);
            float p11 = ((lane < 13) ? 0.0f : d10) + ((lane < 12) ? 0.0f : d11);
            #pragma unroll
            for (int o = 16; o > 0; o >>= 1) {
                p00 += __shfl_xor_sync(0xffffffffu, p00, o);
                p01 += __shfl_xor_sync(0xffffffffu, p01, o);
                p10 += __shfl_xor_sync(0xffffffffu, p10, o);
                p11 += __shfl_xor_sync(0xffffffffu, p11, o);
            }
            float ex00 = __expf(p00 * SCALE), ex01 = __expf(p01 * SCALE);
            float ex10 = __expf(p10 * SCALE), ex11 = __expf(p11 * SCALE);
            if (lane == 0) red2(&g_denom[(size_t)d0 * 2], ex00, ex01);
            if (lane == 1 && v1) red2(&g_denom[(size_t)d1 * 2], ex10, ex11);
            if (lane < 25) {
                float w00 = (lane < 13) ? ex00 : ex01;
                float w01 = (lane < 12) ? ex00 : ex01;
                red4(g_acc + (size_t)d0 * 100 + lq * 4,
                     w00 * (vv0.x + e40.x), w00 * (vv0.y + e40.y),
                     w01 * (vv0.z + e40.z), w01 * (vv0.w + e40.w));
                if (v1) {
                    float w10 = (lane < 13) ? ex10 : ex11;
                    float w11 = (lane < 12) ? ex10 : ex11;
                    red4(g_acc + (size_t)d1 * 100 + lq * 4,
                         w10 * (vv1.x + e41.x), w10 * (vv1.y + e41.y),
                         w11 * (vv1.z + e41.z), w11 * (vv1.w + e41.w));
                }
            }
        }
    }
}

// ---------------------------------------------------------------------------
__global__ void k_final(float* __restrict__ out, int n) {
    int tot = n * 25;
    for (int i = blockIdx.x * blockDim.x + threadIdx.x; i < tot;
         i += gridDim.x * blockDim.x) {
        int nd = i / 25, q = i % 25;
        float den0 = g_denom[(size_t)nd * 2 + 0];
        float den1 = g_denom[(size_t)nd * 2 + 1];
        float dxy = (q < 13) ? den0 : den1;
        float dzw = (q < 12) ? den0 : den1;
        float rxy = (dxy > 0.0f) ? (1.0f / dxy) : 0.0f;
        float rzw = (dzw > 0.0f) ? (1.0f / dzw) : 0.0f;
        float4 a4 = ((const float4*)g_acc)[i];
        float4 sk = ((const float4*)g_skip)[i];
        float4 o;
        o.x = a4.x * rxy + sk.x;
        o.y = a4.y * rxy + sk.y;
        o.z = a4.z * rzw + sk.z;
        o.w = a4.w * rzw + sk.w;
        ((float4*)out)[i] = o;
    }
}

// ---------------------------------------------------------------------------
extern "C" void kernel_launch(void* const* d_in, const int* in_sizes, int n_in,
                              void* d_out, int out_size) {
    const float* x   = (const float*)d_in[0];
    const float* lu  = (const float*)d_in[1];
    const float* t   = (const float*)d_in[2];
    const float* msg = (const float*)d_in[3];
    const float* Wt  = (const float*)d_in[4];
    const float* bt  = (const float*)d_in[5];
    const float* Wq  = (const float*)d_in[6];
    const float* bq  = (const float*)d_in[7];
    const float* Wk  = (const float*)d_in[8];
    const float* bk  = (const float*)d_in[9];
    const float* Wv  = (const float*)d_in[10];
    const float* bv  = (const float*)d_in[11];
    const float* We  = (const float*)d_in[12];
    const float* Ws  = (const float*)d_in[13];
    const float* bs  = (const float*)d_in[14];
    const int*   ei  = (const int*)d_in[15];

    int n  = in_sizes[1];
    int ne = in_sizes[2];
    float* out = (float*)d_out;

    int dev = 0;
    cudaGetDevice(&dev);
    int nsm = 148;
    cudaDeviceGetAttribute(&nsm, cudaDevAttrMultiProcessorCount, dev);

    cudaFuncSetAttribute(k_nproj, cudaFuncAttributeMaxDynamicSharedMemorySize, SMEM_NP_BYTES);
    cudaFuncSetAttribute(k_edge,  cudaFuncAttributeMaxDynamicSharedMemorySize, SMEM_EDGE_BYTES);

    k_nproj<<<nsm * 2, 512, SMEM_NP_BYTES>>>(x, Wq, bq, Wk, bk, Wv, bv, Ws, bs, n);
    k_edge<<<nsm * 2, 384, SMEM_EDGE_BYTES>>>(lu, t, msg, Wt, bt, We, ei, n, ne);
    k_final<<<4096, 256>>>(out, n);
}